// round 7
// baseline (speedup 1.0000x reference)
#include <cuda_runtime.h>
#include <cuda_fp16.h>
#include <cstdint>

// ---------------- problem constants ----------------
#define BB 16
#define EE 8
#define CC 1024
#define DD 512
#define FF 2048

// ---------------- tiling ----------------
#define BM 128
#define BN 128
#define BK 64
#define KSB 144                        // smem row stride in BYTES (72 halfs): conflict-free
#define A_BYTES (BM * KSB)             // 18432
#define STAGE_BYTES (2 * A_BYTES)      // A + B tiles = 36864
#define NSTAGE 3
#define BIAS_OFF (NSTAGE * STAGE_BYTES)        // 110592
#define SMEM_TOTAL (BIAS_OFF + BN * 4)         // 111104 -> 2 CTAs/SM
#define NTHREADS 128

// ---------------- scratch (device globals; no allocs) ----------------
__device__ __half g_Xh [(size_t)BB * EE * CC * DD];      // X  fp16
__device__ __half g_W1t[(size_t)EE * FF * DD];           // W1^T [e][n=F][k=D] fp16
__device__ __half g_W2t[(size_t)EE * DD * FF];           // W2^T [e][n=D][k=F] fp16
__device__ __half g_Hh [(size_t)BB * EE * CC * FF];      // H  fp16

// ---------------- PTX helpers ----------------
__device__ __forceinline__ uint32_t smem_u32(const void* p) {
    uint32_t a;
    asm("{ .reg .u64 t; cvta.to.shared.u64 t, %1; cvt.u32.u64 %0, t; }" : "=r"(a) : "l"(p));
    return a;
}
#define CP_ASYNC16(dst, src) \
    asm volatile("cp.async.cg.shared.global [%0], [%1], 16;" :: "r"(dst), "l"(src) : "memory")
#define CP_COMMIT()  asm volatile("cp.async.commit_group;" ::: "memory")
#define CP_WAIT1()   asm volatile("cp.async.wait_group 1;" ::: "memory")

__device__ __forceinline__ void ldsm4(uint32_t* r, uint32_t addr) {
    asm volatile("ldmatrix.sync.aligned.m8n8.x4.shared.b16 {%0,%1,%2,%3}, [%4];"
        : "=r"(r[0]), "=r"(r[1]), "=r"(r[2]), "=r"(r[3]) : "r"(addr));
}
__device__ __forceinline__ void mma16816(float* c, const uint32_t* a, const uint32_t* b) {
    asm volatile("mma.sync.aligned.m16n8k16.row.col.f32.f16.f16.f32 "
        "{%0,%1,%2,%3}, {%4,%5,%6,%7}, {%8,%9}, {%0,%1,%2,%3};"
        : "+f"(c[0]), "+f"(c[1]), "+f"(c[2]), "+f"(c[3])
        : "r"(a[0]), "r"(a[1]), "r"(a[2]), "r"(a[3]), "r"(b[0]), "r"(b[1]));
}

// ---------------- math helpers ----------------
__device__ __forceinline__ float gelu_fast(float x) {
    // gelu_tanh(x) = x / (1 + exp(-2u)),  u = 0.79788456(x + 0.044715 x^3)
    float x2 = x * x;
    float t  = fmaf(0.044715f * x2, 1.0f, 1.0f);         // 1 + 0.044715 x^2
    float m  = x * t;                                    // x + 0.044715 x^3
    float y  = -2.302590141462743f * m;                  // -2*0.79788456/ln2 * m
    float z;
    asm("ex2.approx.f32 %0, %1;" : "=f"(z) : "f"(y));    // exp(-2u)
    float d;
    asm("rcp.approx.f32 %0, %1;" : "=f"(d) : "f"(z + 1.0f));
    return x * d;
}

// ---------------- prepass: fp32 -> fp16 (coalesced) ----------------
__global__ void to_fp16(const float* __restrict__ src, __half* __restrict__ dst, size_t n4) {
    size_t i = blockIdx.x * (size_t)blockDim.x + threadIdx.x;
    if (i >= n4) return;
    float4 v = reinterpret_cast<const float4*>(src)[i];
    __half2 h0 = __floats2half2_rn(v.x, v.y);
    __half2 h1 = __floats2half2_rn(v.z, v.w);
    uint2 u;
    u.x = *reinterpret_cast<unsigned*>(&h0);
    u.y = *reinterpret_cast<unsigned*>(&h1);
    reinterpret_cast<uint2*>(dst)[i] = u;
}

// ---------------- prepass: tiled transpose  w[e][K][N] -> t[e][N][K] fp16 ----------------
__global__ void transpose_fp16(const float* __restrict__ w, __half* __restrict__ t,
                               int K, int N) {
    __shared__ float tile[32][33];
    const int e = blockIdx.z;
    const int k0 = blockIdx.y * 32;
    const int n0 = blockIdx.x * 32;
    const float* we = w + (size_t)e * K * N;
#pragma unroll
    for (int i = 0; i < 4; i++) {
        int k = k0 + threadIdx.y + i * 8;
        tile[threadIdx.y + i * 8][threadIdx.x] = we[(size_t)k * N + n0 + threadIdx.x];
    }
    __syncthreads();
    __half* te = t + (size_t)e * N * K;
#pragma unroll
    for (int i = 0; i < 4; i++) {
        int n = n0 + threadIdx.y + i * 8;
        te[(size_t)n * K + k0 + threadIdx.x] = __float2half_rn(tile[threadIdx.x][threadIdx.y + i * 8]);
    }
}

// ---------------- main grouped GEMM (raw mma.m16n8k16, register epilogue) ----------------
// 128 threads / 4 warps, warp tile 64x64, CTA tile 128x128, cp.async 3-stage.
// C = A[128xK] @ B[128xK]^T + bias ; mode0: gelu -> Oh (fp16) ; mode1: -> outF (fp32)
__global__ void __launch_bounds__(NTHREADS)
moe_gemm(const __half* __restrict__ Ah, const __half* __restrict__ Bh,
         const float* __restrict__ bias,
         float* __restrict__ outF, __half* __restrict__ Oh,
         int K, int Ntot, int mode)
{
    extern __shared__ char smc[];
    const uint32_t sbase = smem_u32(smc);
    const int tid = threadIdx.x;
    const int lane = tid & 31;
    const int wid = tid >> 5;

    const int g = blockIdx.z;
    const int e = g & (EE - 1);
    const int mBase = blockIdx.y * BM;
    const int nBase = blockIdx.x * BN;

    const __half* aP = Ah + (size_t)g * CC * K + (size_t)mBase * K;
    const __half* bP = Bh + (size_t)e * Ntot * K + (size_t)nBase * K;

    // ---- cp.async thread slots (hoisted addressing) ----
    const int cRow = tid >> 3;            // 0..15
    const int cQ   = tid & 7;             // 16B chunk within 128B row
    const __half* aSrc = aP + (size_t)cRow * K + cQ * 8;
    const __half* bSrc = bP + (size_t)cRow * K + cQ * 8;
    const uint32_t dOff = (uint32_t)(cRow * KSB + cQ * 16);
    const size_t step16 = (size_t)16 * K;    // 16 rows

    auto loadStage = [&](int kt) {
        const uint32_t s = sbase + (uint32_t)((kt % NSTAGE) * STAGE_BYTES) + dOff;
        const __half* aS = aSrc + (size_t)kt * BK;
        const __half* bS = bSrc + (size_t)kt * BK;
#pragma unroll
        for (int i = 0; i < 8; i++)
            CP_ASYNC16(s + i * (16 * KSB), aS + i * step16);
#pragma unroll
        for (int i = 0; i < 8; i++)
            CP_ASYNC16(s + A_BYTES + i * (16 * KSB), bS + i * step16);
    };

    // ---- warp layout: 2(M) x 2(N), warp tile 64x64 ----
    const int wm = (wid & 1) * 64;
    const int wn = (wid >> 1) * 64;

    // ldmatrix per-lane base addresses (stage 0)
    // A x4: r0=(rows0-7,k0-7) r1=(rows8-15,k0-7) r2=(rows0-7,k8-15) r3=(rows8-15,k8-15)
    const uint32_t aLd0 = sbase
        + (uint32_t)((wm + (lane & 15)) * KSB + (lane >> 4) * 16);
    // B x4: r0=(n0-7,k0-7) r1=(n0-7,k8-15) r2=(n8-15,k0-7) r3=(n8-15,k8-15)
    const uint32_t bLd0 = sbase + A_BYTES
        + (uint32_t)((wn + ((lane >> 4) & 1) * 8 + (lane & 7)) * KSB + ((lane >> 3) & 1) * 16);

    float acc[4][8][4];
#pragma unroll
    for (int mi = 0; mi < 4; mi++)
#pragma unroll
        for (int ni = 0; ni < 8; ni++)
#pragma unroll
            for (int q = 0; q < 4; q++) acc[mi][ni][q] = 0.0f;

    loadStage(0); CP_COMMIT();
    loadStage(1); CP_COMMIT();
    // stage bias once (covered by first mainloop __syncthreads)
    *(float*)(smc + BIAS_OFF + tid * 4) = bias[nBase + tid];

    const int KT = K / BK;
    for (int kt = 0; kt < KT; kt++) {
        CP_WAIT1();                    // stage kt landed
        __syncthreads();               // visibility + slot-reuse safety
        if (kt + 2 < KT) loadStage(kt + 2);
        CP_COMMIT();                   // unconditional: uniform group accounting

        const uint32_t so = (uint32_t)((kt % NSTAGE) * STAGE_BYTES);
        const uint32_t aLd = aLd0 + so;
        const uint32_t bLd = bLd0 + so;

#pragma unroll
        for (int ks = 0; ks < 4; ks++) {
            uint32_t af[4][4], bf[4][4];
#pragma unroll
            for (int mi = 0; mi < 4; mi++)
                ldsm4(af[mi], aLd + mi * (16 * KSB) + ks * 32);
#pragma unroll
            for (int nj = 0; nj < 4; nj++)
                ldsm4(bf[nj], bLd + nj * (16 * KSB) + ks * 32);
#pragma unroll
            for (int mi = 0; mi < 4; mi++)
#pragma unroll
                for (int nj = 0; nj < 4; nj++) {
                    mma16816(acc[mi][2 * nj],     af[mi], &bf[nj][0]);
                    mma16816(acc[mi][2 * nj + 1], af[mi], &bf[nj][2]);
                }
        }
    }

    // ---- register epilogue: bias + (gelu) + direct stores, no staging ----
    const float* sbias = (const float*)(smc + BIAS_OFF);
    const int r  = lane >> 2;           // acc row within 16-row tile
    const int c2 = (lane & 3) * 2;      // acc col pair within 8-col tile

    float2 bb[8];
#pragma unroll
    for (int ni = 0; ni < 8; ni++)
        bb[ni] = *(const float2*)&sbias[wn + ni * 8 + c2];

    const size_t outBase = (size_t)g * CC * Ntot
                         + (size_t)(mBase + wm + r) * Ntot + nBase + wn + c2;

    if (mode == 0) {
#pragma unroll
        for (int mi = 0; mi < 4; mi++) {
            const size_t ro0 = outBase + (size_t)(mi * 16) * Ntot;
            const size_t ro1 = ro0 + (size_t)8 * Ntot;
#pragma unroll
            for (int ni = 0; ni < 8; ni++) {
                const float* a = acc[mi][ni];
                __half2 h01 = __floats2half2_rn(gelu_fast(a[0] + bb[ni].x),
                                                gelu_fast(a[1] + bb[ni].y));
                __half2 h23 = __floats2half2_rn(gelu_fast(a[2] + bb[ni].x),
                                                gelu_fast(a[3] + bb[ni].y));
                *reinterpret_cast<__half2*>(Oh + ro0 + ni * 8) = h01;
                *reinterpret_cast<__half2*>(Oh + ro1 + ni * 8) = h23;
            }
        }
    } else {
#pragma unroll
        for (int mi = 0; mi < 4; mi++) {
            const size_t ro0 = outBase + (size_t)(mi * 16) * Ntot;
            const size_t ro1 = ro0 + (size_t)8 * Ntot;
#pragma unroll
            for (int ni = 0; ni < 8; ni++) {
                const float* a = acc[mi][ni];
                *reinterpret_cast<float2*>(outF + ro0 + ni * 8) =
                    make_float2(a[0] + bb[ni].x, a[1] + bb[ni].y);
                *reinterpret_cast<float2*>(outF + ro1 + ni * 8) =
                    make_float2(a[2] + bb[ni].x, a[3] + bb[ni].y);
            }
        }
    }
}

// ---------------- host launcher ----------------
extern "C" void kernel_launch(void* const* d_in, const int* in_sizes, int n_in,
                              void* d_out, int out_size) {
    const float* inputs = (const float*)d_in[0];   // [B, E*C, D]
    const float* w1     = (const float*)d_in[1];   // [E, D, F]
    const float* b1     = (const float*)d_in[2];   // [E, F]
    const float* w2     = (const float*)d_in[3];   // [E, F, D]
    const float* b2     = (const float*)d_in[4];   // [E, D]
    float*       out    = (float*)d_out;           // [B, E*C, D]

    void *xh, *w1t, *w2t, *hh;
    cudaGetSymbolAddress(&xh, g_Xh);
    cudaGetSymbolAddress(&w1t, g_W1t);
    cudaGetSymbolAddress(&w2t, g_W2t);
    cudaGetSymbolAddress(&hh, g_Hh);

    cudaFuncSetAttribute(moe_gemm, cudaFuncAttributeMaxDynamicSharedMemorySize, SMEM_TOTAL);

    // prepass
    {
        size_t n4 = (size_t)BB * EE * CC * DD / 4;
        to_fp16<<<(unsigned)((n4 + 255) / 256), 256>>>(inputs, (__half*)xh, n4);
    }
    {
        dim3 blk(32, 8);
        dim3 g1(FF / 32, DD / 32, EE);
        transpose_fp16<<<g1, blk>>>(w1, (__half*)w1t, DD, FF);
        dim3 g2(DD / 32, FF / 32, EE);
        transpose_fp16<<<g2, blk>>>(w2, (__half*)w2t, FF, DD);
    }

    // GEMM1: H = gelu(X @ W1 + b1): per group M=1024, K=512, N=2048
    {
        dim3 grid(FF / BN, CC / BM, BB * EE);
        moe_gemm<<<grid, NTHREADS, SMEM_TOTAL>>>(
            (const __half*)xh, (const __half*)w1t, b1,
            nullptr, (__half*)hh, DD, FF, 0);
    }
    // GEMM2: Y = H @ W2 + b2: per group M=1024, K=2048, N=512
    {
        dim3 grid(DD / BN, CC / BM, BB * EE);
        moe_gemm<<<grid, NTHREADS, SMEM_TOTAL>>>(
            (const __half*)hh, (const __half*)w2t, b2,
            out, nullptr, FF, DD, 1);
    }
}

// round 8
// speedup vs baseline: 1.5166x; 1.5166x over previous
#include <cuda_runtime.h>
#include <cuda_fp16.h>
#include <mma.h>
#include <cstdint>

using namespace nvcuda;

// ---------------- problem constants ----------------
#define BB 16
#define EE 8
#define CC 1024
#define DD 512
#define FF 2048

// ---------------- shared tiling constants ----------------
#define BM 128
#define BK 64
#define NSTAGE 3

// ---- GEMM1 (f16-acc raw mma) : 128 threads, CTA 128x128, warp 64x64 ----
#define G1_BN 128
#define KSB 144                        // smem row stride BYTES (72 halfs), conflict-free
#define G1_A_BYTES (BM * KSB)          // 18432
#define G1_STAGE (2 * G1_A_BYTES)      // 36864
#define G1_BIAS_OFF (NSTAGE * G1_STAGE)         // 110592
#define G1_SMEM (G1_BIAS_OFF + G1_BN * 4)       // 111104
#define G1_EPI 132                     // f32 staging stride

// ---- GEMM2 (wmma f32-acc, round-4 proven) : 256 threads, CTA 128x128 ----
#define KS 72                          // smem row stride in halfs
#define G2_STAGE ((BM + 128) * KS * 2) // 36864
#define G2_SMEM (NSTAGE * G2_STAGE)    // 110592
#define G2_EPI 132

// ---------------- scratch (device globals; no allocs) ----------------
__device__ __half g_Xh [(size_t)BB * EE * CC * DD];
__device__ __half g_W1t[(size_t)EE * FF * DD];   // [e][n=F][k=D]
__device__ __half g_W2t[(size_t)EE * DD * FF];   // [e][n=D][k=F]
__device__ __half g_Hh [(size_t)BB * EE * CC * FF];

// ---------------- PTX helpers ----------------
__device__ __forceinline__ uint32_t smem_u32(const void* p) {
    uint32_t a;
    asm("{ .reg .u64 t; cvta.to.shared.u64 t, %1; cvt.u32.u64 %0, t; }" : "=r"(a) : "l"(p));
    return a;
}
#define CP_ASYNC16(dst, src) \
    asm volatile("cp.async.cg.shared.global [%0], [%1], 16;" :: "r"(dst), "l"(src) : "memory")
#define CP_COMMIT()  asm volatile("cp.async.commit_group;" ::: "memory")
#define CP_WAIT1()   asm volatile("cp.async.wait_group 1;" ::: "memory")

__device__ __forceinline__ void ldsm4(uint32_t* r, uint32_t addr) {
    asm volatile("ldmatrix.sync.aligned.m8n8.x4.shared.b16 {%0,%1,%2,%3}, [%4];"
        : "=r"(r[0]), "=r"(r[1]), "=r"(r[2]), "=r"(r[3]) : "r"(addr));
}
// f16-accumulate k16 MMA: D(2xh2) = A*B + C   (C may differ from D)
__device__ __forceinline__ void mma_f16acc(uint32_t* d, const uint32_t* a, const uint32_t* b,
                                           const uint32_t* c) {
    asm volatile("mma.sync.aligned.m16n8k16.row.col.f16.f16.f16.f16 "
        "{%0,%1}, {%2,%3,%4,%5}, {%6,%7}, {%8,%9};"
        : "=r"(d[0]), "=r"(d[1])
        : "r"(a[0]), "r"(a[1]), "r"(a[2]), "r"(a[3]), "r"(b[0]), "r"(b[1]),
          "r"(c[0]), "r"(c[1]));
}
// promote: D_f32(16x8) += Chunk(16x8 as A-frag) @ I8 (k8 MMA)
__device__ __forceinline__ void mma_promote(float* d, const uint32_t* a, uint32_t ib) {
    asm volatile("mma.sync.aligned.m16n8k8.row.col.f32.f16.f16.f32 "
        "{%0,%1,%2,%3}, {%4,%5}, {%6}, {%0,%1,%2,%3};"
        : "+f"(d[0]), "+f"(d[1]), "+f"(d[2]), "+f"(d[3])
        : "r"(a[0]), "r"(a[1]), "r"(ib));
}

// ---------------- math helpers ----------------
__device__ __forceinline__ float gelu_fast(float x) {
    float u = 0.7978845608028654f * fmaf(0.044715f * x, x * x, x);
    float y = 2.8853900817779268f * u;     // 2u / ln2
    float z;
    asm("ex2.approx.f32 %0, %1;" : "=f"(z) : "f"(y));
    float t = 1.0f - __fdividef(2.0f, z + 1.0f);
    return 0.5f * x * (1.0f + t);
}

// ---------------- prepass kernels ----------------
__global__ void to_fp16(const float* __restrict__ src, __half* __restrict__ dst, size_t n4) {
    size_t i = blockIdx.x * (size_t)blockDim.x + threadIdx.x;
    if (i >= n4) return;
    float4 v = reinterpret_cast<const float4*>(src)[i];
    __half2 h0 = __floats2half2_rn(v.x, v.y);
    __half2 h1 = __floats2half2_rn(v.z, v.w);
    uint2 u;
    u.x = *reinterpret_cast<unsigned*>(&h0);
    u.y = *reinterpret_cast<unsigned*>(&h1);
    reinterpret_cast<uint2*>(dst)[i] = u;
}

__global__ void transpose_fp16(const float* __restrict__ w, __half* __restrict__ t,
                               int K, int N) {
    __shared__ float tile[32][33];
    const int e = blockIdx.z;
    const int k0 = blockIdx.y * 32;
    const int n0 = blockIdx.x * 32;
    const float* we = w + (size_t)e * K * N;
#pragma unroll
    for (int i = 0; i < 4; i++) {
        int k = k0 + threadIdx.y + i * 8;
        tile[threadIdx.y + i * 8][threadIdx.x] = we[(size_t)k * N + n0 + threadIdx.x];
    }
    __syncthreads();
    __half* te = t + (size_t)e * N * K;
#pragma unroll
    for (int i = 0; i < 4; i++) {
        int n = n0 + threadIdx.y + i * 8;
        te[(size_t)n * K + k0 + threadIdx.x] = __float2half_rn(tile[threadIdx.x][threadIdx.y + i * 8]);
    }
}

// ================= GEMM1: H = gelu(X@W1^T + b1), f16-acc chunks =================
// 128 threads / 4 warps (2x2), warp tile 64x64, CTA 128x128, K=512.
__global__ void __launch_bounds__(128)
moe_gemm1_f16acc(const __half* __restrict__ Ah, const __half* __restrict__ Bh,
                 const float* __restrict__ bias, __half* __restrict__ Oh,
                 int K, int Ntot)
{
    extern __shared__ char smc[];
    const uint32_t sbase = smem_u32(smc);
    const int tid = threadIdx.x;
    const int lane = tid & 31;
    const int wid = tid >> 5;

    const int g = blockIdx.z;
    const int e = g & (EE - 1);
    const int mBase = blockIdx.y * BM;
    const int nBase = blockIdx.x * G1_BN;

    const __half* aP = Ah + (size_t)g * CC * K + (size_t)mBase * K;
    const __half* bP = Bh + (size_t)e * Ntot * K + (size_t)nBase * K;

    // cp.async slots
    const int cRow = tid >> 3, cQ = tid & 7;
    const __half* aSrc = aP + (size_t)cRow * K + cQ * 8;
    const __half* bSrc = bP + (size_t)cRow * K + cQ * 8;
    const uint32_t dOff = (uint32_t)(cRow * KSB + cQ * 16);
    const size_t step16 = (size_t)16 * K;

    auto loadStage = [&](int kt) {
        const uint32_t s = sbase + (uint32_t)((kt % NSTAGE) * G1_STAGE) + dOff;
        const __half* aS = aSrc + (size_t)kt * BK;
        const __half* bS = bSrc + (size_t)kt * BK;
#pragma unroll
        for (int i = 0; i < 8; i++)
            CP_ASYNC16(s + i * (16 * KSB), aS + i * step16);
#pragma unroll
        for (int i = 0; i < 8; i++)
            CP_ASYNC16(s + G1_A_BYTES + i * (16 * KSB), bS + i * step16);
    };

    const int wm = (wid & 1) * 64;
    const int wn = (wid >> 1) * 64;

    // ldmatrix lane bases (verified layout, round 7)
    const uint32_t aLd0 = sbase + (uint32_t)((wm + (lane & 15)) * KSB + (lane >> 4) * 16);
    const uint32_t bLd0 = sbase + G1_A_BYTES
        + (uint32_t)((wn + ((lane >> 4) & 1) * 8 + (lane & 7)) * KSB + ((lane >> 3) & 1) * 16);

    // identity B-fragment for promote (m16n8k8, col-major): b = (I[2c][r], I[2c+1][r])
    uint32_t ib;
    {
        int r = lane >> 2, c = lane & 3;
        __half2 iv = __halves2half2(__float2half(2 * c == r ? 1.0f : 0.0f),
                                    __float2half(2 * c + 1 == r ? 1.0f : 0.0f));
        ib = *reinterpret_cast<uint32_t*>(&iv);
    }
    uint32_t zz[2] = {0u, 0u};

    float acc[4][8][4];
#pragma unroll
    for (int mi = 0; mi < 4; mi++)
#pragma unroll
        for (int n8 = 0; n8 < 8; n8++)
#pragma unroll
            for (int q = 0; q < 4; q++) acc[mi][n8][q] = 0.0f;
    uint32_t ch[4][8][2];

    loadStage(0); CP_COMMIT();
    loadStage(1); CP_COMMIT();
    *(float*)(smc + G1_BIAS_OFF + tid * 4) = bias[nBase + tid];

    const int KT = K / BK;       // 8
    for (int kt = 0; kt < KT; kt++) {
        CP_WAIT1();
        __syncthreads();
        if (kt + 2 < KT) loadStage(kt + 2);
        CP_COMMIT();

        const uint32_t so = (uint32_t)((kt % NSTAGE) * G1_STAGE);
        const uint32_t aLd = aLd0 + so;
        const uint32_t bLd = bLd0 + so;

#pragma unroll
        for (int ks = 0; ks < 4; ks++) {
            uint32_t bf[4][4];
#pragma unroll
            for (int nj = 0; nj < 4; nj++)
                ldsm4(bf[nj], bLd + nj * (16 * KSB) + ks * 32);
#pragma unroll
            for (int mi = 0; mi < 4; mi++) {
                uint32_t af[4];
                ldsm4(af, aLd + mi * (16 * KSB) + ks * 32);
#pragma unroll
                for (int nj = 0; nj < 4; nj++) {
                    // chunk start (even ks): C = 0; else accumulate into chunk
                    if ((ks & 1) == 0) {
                        mma_f16acc(ch[mi][2 * nj],     af, &bf[nj][0], zz);
                        mma_f16acc(ch[mi][2 * nj + 1], af, &bf[nj][2], zz);
                    } else {
                        mma_f16acc(ch[mi][2 * nj],     af, &bf[nj][0], ch[mi][2 * nj]);
                        mma_f16acc(ch[mi][2 * nj + 1], af, &bf[nj][2], ch[mi][2 * nj + 1]);
                    }
                }
            }
            if (ks & 1) {   // promote chunk -> f32 master on the tensor pipe
#pragma unroll
                for (int mi = 0; mi < 4; mi++)
#pragma unroll
                    for (int n8 = 0; n8 < 8; n8++)
                        mma_promote(acc[mi][n8], ch[mi][n8], ib);
            }
        }
    }

    // ---- epilogue: stage f32 in smem (coalesced out) ----
    __syncthreads();
    float* stage = reinterpret_cast<float*>(smc);
    const int r  = lane >> 2;
    const int c2 = (lane & 3) * 2;
#pragma unroll
    for (int mi = 0; mi < 4; mi++)
#pragma unroll
        for (int n8 = 0; n8 < 8; n8++) {
            const float* a = acc[mi][n8];
            int row = wm + mi * 16 + r;
            int col = wn + n8 * 8 + c2;
            *reinterpret_cast<float2*>(&stage[row * G1_EPI + col]) = make_float2(a[0], a[1]);
            *reinterpret_cast<float2*>(&stage[(row + 8) * G1_EPI + col]) = make_float2(a[2], a[3]);
        }
    __syncthreads();

    const float* sbias = (const float*)(smc + G1_BIAS_OFF);
#pragma unroll
    for (int i = 0; i < 32; i++) {
        int idx = tid + i * 128;          // float4 index, 0..4095
        int row = idx >> 5;
        int c4 = idx & 31;
        float4 v = *reinterpret_cast<float4*>(&stage[row * G1_EPI + c4 * 4]);
        int n = c4 * 4;
        v.x += sbias[n + 0]; v.y += sbias[n + 1]; v.z += sbias[n + 2]; v.w += sbias[n + 3];
        __half2 h0 = __floats2half2_rn(gelu_fast(v.x), gelu_fast(v.y));
        __half2 h1 = __floats2half2_rn(gelu_fast(v.z), gelu_fast(v.w));
        uint2 u;
        u.x = *reinterpret_cast<unsigned*>(&h0);
        u.y = *reinterpret_cast<unsigned*>(&h1);
        size_t off = (size_t)g * CC * Ntot + (size_t)(mBase + row) * Ntot + nBase + n;
        *reinterpret_cast<uint2*>(Oh + off) = u;
    }
}

// ================= GEMM2: Y = H@W2^T + b2 (round-4 wmma kernel, f32 acc) =================
__global__ void __launch_bounds__(256, 2)
moe_gemm2(const __half* __restrict__ Ah, const __half* __restrict__ Bh,
          const float* __restrict__ bias, float* __restrict__ outF,
          int K, int Ntot)
{
    extern __shared__ char smc[];
    const int tid = threadIdx.x;
    const int wid = tid >> 5;

    const int g = blockIdx.z;
    const int e = g & (EE - 1);
    const int mBase = blockIdx.y * BM;
    const int nBase = blockIdx.x * 128;

    const __half* aP = Ah + (size_t)g * CC * K + (size_t)mBase * K;
    const __half* bP = Bh + (size_t)e * Ntot * K + (size_t)nBase * K;
    const uint32_t sbase = smem_u32(smc);

    const int KT = K / BK;
    auto loadStage = [&](int kt) {
        const int k0 = kt * BK;
        const uint32_t s = sbase + (uint32_t)((kt % NSTAGE) * G2_STAGE);
#pragma unroll
        for (int i = 0; i < 4; i++) {
            int idx = tid + i * 256;
            int row = idx >> 3, q = idx & 7;
            CP_ASYNC16(s + (uint32_t)(row * (KS * 2) + q * 16),
                       aP + (size_t)row * K + k0 + q * 8);
        }
        const uint32_t sb = s + BM * KS * 2;
#pragma unroll
        for (int i = 0; i < 4; i++) {
            int idx = tid + i * 256;
            int row = idx >> 3, q = idx & 7;
            CP_ASYNC16(sb + (uint32_t)(row * (KS * 2) + q * 16),
                       bP + (size_t)row * K + k0 + q * 8);
        }
    };

    wmma::fragment<wmma::accumulator, 16, 16, 16, float> acc[4][2];
#pragma unroll
    for (int mi = 0; mi < 4; mi++)
#pragma unroll
        for (int ni = 0; ni < 2; ni++)
            wmma::fill_fragment(acc[mi][ni], 0.0f);

    const int wm = (wid & 1) * 64;
    const int wn = (wid >> 1) * 32;

    loadStage(0); CP_COMMIT();
    loadStage(1); CP_COMMIT();

    for (int kt = 0; kt < KT; kt++) {
        CP_WAIT1();
        __syncthreads();
        if (kt + 2 < KT) loadStage(kt + 2);
        CP_COMMIT();

        const __half* sA = (const __half*)(smc + (kt % NSTAGE) * G2_STAGE);
        const __half* sB = sA + BM * KS;

#pragma unroll
        for (int ks = 0; ks < 4; ks++) {
            wmma::fragment<wmma::matrix_a, 16, 16, 16, __half, wmma::row_major> fa[4];
            wmma::fragment<wmma::matrix_b, 16, 16, 16, __half, wmma::col_major> fb[2];
#pragma unroll
            for (int mi = 0; mi < 4; mi++)
                wmma::load_matrix_sync(fa[mi], sA + (wm + mi * 16) * KS + ks * 16, KS);
#pragma unroll
            for (int ni = 0; ni < 2; ni++)
                wmma::load_matrix_sync(fb[ni], sB + (wn + ni * 16) * KS + ks * 16, KS);
#pragma unroll
            for (int mi = 0; mi < 4; mi++)
#pragma unroll
                for (int ni = 0; ni < 2; ni++)
                    wmma::mma_sync(acc[mi][ni], fa[mi], fb[ni], acc[mi][ni]);
        }
    }

    __syncthreads();
    float* stage = reinterpret_cast<float*>(smc);
#pragma unroll
    for (int mi = 0; mi < 4; mi++)
#pragma unroll
        for (int ni = 0; ni < 2; ni++)
            wmma::store_matrix_sync(&stage[(wm + mi * 16) * G2_EPI + wn + ni * 16],
                                    acc[mi][ni], G2_EPI, wmma::mem_row_major);
    __syncthreads();

#pragma unroll
    for (int i = 0; i < 16; i++) {
        int idx = tid + i * 256;
        int row = idx >> 5;
        int c4 = idx & 31;
        float4 v = *reinterpret_cast<float4*>(&stage[row * G2_EPI + c4 * 4]);
        int n = nBase + c4 * 4;
        v.x += __ldg(bias + n + 0); v.y += __ldg(bias + n + 1);
        v.z += __ldg(bias + n + 2); v.w += __ldg(bias + n + 3);
        size_t off = (size_t)g * CC * Ntot + (size_t)(mBase + row) * Ntot + n;
        *reinterpret_cast<float4*>(outF + off) = v;
    }
}

// ---------------- host launcher ----------------
extern "C" void kernel_launch(void* const* d_in, const int* in_sizes, int n_in,
                              void* d_out, int out_size) {
    const float* inputs = (const float*)d_in[0];
    const float* w1     = (const float*)d_in[1];
    const float* b1     = (const float*)d_in[2];
    const float* w2     = (const float*)d_in[3];
    const float* b2     = (const float*)d_in[4];
    float*       out    = (float*)d_out;

    void *xh, *w1t, *w2t, *hh;
    cudaGetSymbolAddress(&xh, g_Xh);
    cudaGetSymbolAddress(&w1t, g_W1t);
    cudaGetSymbolAddress(&w2t, g_W2t);
    cudaGetSymbolAddress(&hh, g_Hh);

    cudaFuncSetAttribute(moe_gemm1_f16acc, cudaFuncAttributeMaxDynamicSharedMemorySize, G1_SMEM);
    cudaFuncSetAttribute(moe_gemm2, cudaFuncAttributeMaxDynamicSharedMemorySize, G2_SMEM);

    // prepass
    {
        size_t n4 = (size_t)BB * EE * CC * DD / 4;
        to_fp16<<<(unsigned)((n4 + 255) / 256), 256>>>(inputs, (__half*)xh, n4);
    }
    {
        dim3 blk(32, 8);
        dim3 g1(FF / 32, DD / 32, EE);
        transpose_fp16<<<g1, blk>>>(w1, (__half*)w1t, DD, FF);
        dim3 g2(DD / 32, FF / 32, EE);
        transpose_fp16<<<g2, blk>>>(w2, (__half*)w2t, FF, DD);
    }

    // GEMM1: per group M=1024, K=512, N=2048 (f16-acc chunks)
    {
        dim3 grid(FF / G1_BN, CC / BM, BB * EE);
        moe_gemm1_f16acc<<<grid, 128, G1_SMEM>>>(
            (const __half*)xh, (const __half*)w1t, b1, (__half*)hh, DD, FF);
    }
    // GEMM2: per group M=1024, K=2048, N=512 (wmma f32-acc)
    {
        dim3 grid(DD / 128, CC / BM, BB * EE);
        moe_gemm2<<<grid, 256, G2_SMEM>>>(
            (const __half*)hh, (const __half*)w2t, b2, out, FF, DD);
    }
}

// round 9
// speedup vs baseline: 1.5774x; 1.0401x over previous
#include <cuda_runtime.h>
#include <cuda_fp16.h>
#include <cstdint>

// ---------------- problem constants ----------------
#define BB 16
#define EE 8
#define CC 1024
#define DD 512
#define FF 2048

// ---------------- tiling ----------------
#define BM 128
#define BN 128
#define BK 64
#define KSB 144                        // smem row stride BYTES (72 halfs), conflict-free
#define A_BYTES (BM * KSB)             // 18432
#define STAGE_BYTES (2 * A_BYTES)      // 36864
#define NSTAGE 3
#define BIAS_OFF (NSTAGE * STAGE_BYTES)        // 110592
#define SMEM_TOTAL (BIAS_OFF + BN * 4)         // 111104 -> 2 CTAs/SM
#define EPI_LD 132                     // f32 epilogue staging stride
#define NTHREADS 128

// ---------------- scratch (device globals; no allocs) ----------------
__device__ __half g_Xh [(size_t)BB * EE * CC * DD];
__device__ __half g_W1t[(size_t)EE * FF * DD];   // [e][n=F][k=D]
__device__ __half g_W2t[(size_t)EE * DD * FF];   // [e][n=D][k=F]
__device__ __half g_Hh [(size_t)BB * EE * CC * FF];

// ---------------- PTX helpers ----------------
__device__ __forceinline__ uint32_t smem_u32(const void* p) {
    uint32_t a;
    asm("{ .reg .u64 t; cvta.to.shared.u64 t, %1; cvt.u32.u64 %0, t; }" : "=r"(a) : "l"(p));
    return a;
}
#define CP_ASYNC16(dst, src) \
    asm volatile("cp.async.cg.shared.global [%0], [%1], 16;" :: "r"(dst), "l"(src) : "memory")
#define CP_COMMIT()  asm volatile("cp.async.commit_group;" ::: "memory")
#define CP_WAIT1()   asm volatile("cp.async.wait_group 1;" ::: "memory")

__device__ __forceinline__ void ldsm4(uint32_t* r, uint32_t addr) {
    asm volatile("ldmatrix.sync.aligned.m8n8.x4.shared.b16 {%0,%1,%2,%3}, [%4];"
        : "=r"(r[0]), "=r"(r[1]), "=r"(r[2]), "=r"(r[3]) : "r"(addr));
}
__device__ __forceinline__ void mma16816(float* c, const uint32_t* a, const uint32_t* b) {
    asm volatile("mma.sync.aligned.m16n8k16.row.col.f32.f16.f16.f32 "
        "{%0,%1,%2,%3}, {%4,%5,%6,%7}, {%8,%9}, {%0,%1,%2,%3};"
        : "+f"(c[0]), "+f"(c[1]), "+f"(c[2]), "+f"(c[3])
        : "r"(a[0]), "r"(a[1]), "r"(a[2]), "r"(a[3]), "r"(b[0]), "r"(b[1]));
}

// ---------------- math helpers ----------------
__device__ __forceinline__ float gelu_fast(float x) {
    float u = 0.7978845608028654f * fmaf(0.044715f * x, x * x, x);
    float y = 2.8853900817779268f * u;     // 2u / ln2
    float z;
    asm("ex2.approx.f32 %0, %1;" : "=f"(z) : "f"(y));
    float t = 1.0f - __fdividef(2.0f, z + 1.0f);
    return 0.5f * x * (1.0f + t);
}

// ---------------- prepass kernels ----------------
__global__ void to_fp16(const float* __restrict__ src, __half* __restrict__ dst, size_t n4) {
    size_t i = blockIdx.x * (size_t)blockDim.x + threadIdx.x;
    if (i >= n4) return;
    float4 v = reinterpret_cast<const float4*>(src)[i];
    __half2 h0 = __floats2half2_rn(v.x, v.y);
    __half2 h1 = __floats2half2_rn(v.z, v.w);
    uint2 u;
    u.x = *reinterpret_cast<unsigned*>(&h0);
    u.y = *reinterpret_cast<unsigned*>(&h1);
    reinterpret_cast<uint2*>(dst)[i] = u;
}

__global__ void transpose_fp16(const float* __restrict__ w, __half* __restrict__ t,
                               int K, int N) {
    __shared__ float tile[32][33];
    const int e = blockIdx.z;
    const int k0 = blockIdx.y * 32;
    const int n0 = blockIdx.x * 32;
    const float* we = w + (size_t)e * K * N;
#pragma unroll
    for (int i = 0; i < 4; i++) {
        int k = k0 + threadIdx.y + i * 8;
        tile[threadIdx.y + i * 8][threadIdx.x] = we[(size_t)k * N + n0 + threadIdx.x];
    }
    __syncthreads();
    __half* te = t + (size_t)e * N * K;
#pragma unroll
    for (int i = 0; i < 4; i++) {
        int n = n0 + threadIdx.y + i * 8;
        te[(size_t)n * K + k0 + threadIdx.x] = __float2half_rn(tile[threadIdx.x][threadIdx.y + i * 8]);
    }
}

// ---------------- main grouped GEMM (raw mma, frag double-buffer, staged epilogue) ----------------
// 128 threads / 4 warps (2x2), warp tile 64x64, CTA 128x128, cp.async 3-stage.
// mode0: gelu(A@B^T+bias) -> Oh fp16 ; mode1: A@B^T+bias -> outF fp32
__global__ void __launch_bounds__(NTHREADS)
moe_gemm(const __half* __restrict__ Ah, const __half* __restrict__ Bh,
         const float* __restrict__ bias,
         float* __restrict__ outF, __half* __restrict__ Oh,
         int K, int Ntot, int mode)
{
    extern __shared__ char smc[];
    const uint32_t sbase = smem_u32(smc);
    const int tid = threadIdx.x;
    const int lane = tid & 31;
    const int wid = tid >> 5;

    const int g = blockIdx.z;
    const int e = g & (EE - 1);
    const int mBase = blockIdx.y * BM;
    const int nBase = blockIdx.x * BN;

    const __half* aP = Ah + (size_t)g * CC * K + (size_t)mBase * K;
    const __half* bP = Bh + (size_t)e * Ntot * K + (size_t)nBase * K;

    // cp.async slots (hoisted)
    const int cRow = tid >> 3, cQ = tid & 7;
    const __half* aSrc = aP + (size_t)cRow * K + cQ * 8;
    const __half* bSrc = bP + (size_t)cRow * K + cQ * 8;
    const uint32_t dOff = (uint32_t)(cRow * KSB + cQ * 16);
    const size_t step16 = (size_t)16 * K;

    auto loadStage = [&](int kt) {
        const uint32_t s = sbase + (uint32_t)((kt % NSTAGE) * STAGE_BYTES) + dOff;
        const __half* aS = aSrc + (size_t)kt * BK;
        const __half* bS = bSrc + (size_t)kt * BK;
#pragma unroll
        for (int i = 0; i < 8; i++)
            CP_ASYNC16(s + i * (16 * KSB), aS + i * step16);
#pragma unroll
        for (int i = 0; i < 8; i++)
            CP_ASYNC16(s + A_BYTES + i * (16 * KSB), bS + i * step16);
    };

    const int wm = (wid & 1) * 64;
    const int wn = (wid >> 1) * 64;

    // ldmatrix lane bases (layout verified rounds 7/8)
    const uint32_t aLd0 = sbase + (uint32_t)((wm + (lane & 15)) * KSB + (lane >> 4) * 16);
    const uint32_t bLd0 = sbase + A_BYTES
        + (uint32_t)((wn + ((lane >> 4) & 1) * 8 + (lane & 7)) * KSB + ((lane >> 3) & 1) * 16);

    float acc[4][8][4];
#pragma unroll
    for (int mi = 0; mi < 4; mi++)
#pragma unroll
        for (int n8 = 0; n8 < 8; n8++)
#pragma unroll
            for (int q = 0; q < 4; q++) acc[mi][n8][q] = 0.0f;

    uint32_t af[2][4][4], bf[2][4][4];

    loadStage(0); CP_COMMIT();
    loadStage(1); CP_COMMIT();
    *(float*)(smc + BIAS_OFF + tid * 4) = bias[nBase + tid];

    const int KT = K / BK;
    for (int kt = 0; kt < KT; kt++) {
        CP_WAIT1();
        __syncthreads();
        if (kt + 2 < KT) loadStage(kt + 2);
        CP_COMMIT();

        const uint32_t so = (uint32_t)((kt % NSTAGE) * STAGE_BYTES);
        const uint32_t aLd = aLd0 + so;
        const uint32_t bLd = bLd0 + so;

        // prime ks=0 fragments
#pragma unroll
        for (int mi = 0; mi < 4; mi++) ldsm4(af[0][mi], aLd + mi * (16 * KSB));
#pragma unroll
        for (int nj = 0; nj < 4; nj++) ldsm4(bf[0][nj], bLd + nj * (16 * KSB));

#pragma unroll
        for (int ks = 0; ks < 4; ks++) {
            const int cur = ks & 1, nxt = cur ^ 1;
            if (ks < 3) {   // prefetch ks+1 frags; consumed only next iteration
#pragma unroll
                for (int mi = 0; mi < 4; mi++)
                    ldsm4(af[nxt][mi], aLd + mi * (16 * KSB) + (ks + 1) * 32);
#pragma unroll
                for (int nj = 0; nj < 4; nj++)
                    ldsm4(bf[nxt][nj], bLd + nj * (16 * KSB) + (ks + 1) * 32);
            }
#pragma unroll
            for (int mi = 0; mi < 4; mi++)
#pragma unroll
                for (int nj = 0; nj < 4; nj++) {
                    mma16816(acc[mi][2 * nj],     af[cur][mi], &bf[cur][nj][0]);
                    mma16816(acc[mi][2 * nj + 1], af[cur][mi], &bf[cur][nj][2]);
                }
        }
    }

    // ---- epilogue: stage f32 in smem (coalesced output) ----
    __syncthreads();
    float* stage = reinterpret_cast<float*>(smc);
    const int r  = lane >> 2;
    const int c2 = (lane & 3) * 2;
#pragma unroll
    for (int mi = 0; mi < 4; mi++)
#pragma unroll
        for (int n8 = 0; n8 < 8; n8++) {
            const float* a = acc[mi][n8];
            int row = wm + mi * 16 + r;
            int col = wn + n8 * 8 + c2;
            *reinterpret_cast<float2*>(&stage[row * EPI_LD + col]) = make_float2(a[0], a[1]);
            *reinterpret_cast<float2*>(&stage[(row + 8) * EPI_LD + col]) = make_float2(a[2], a[3]);
        }
    __syncthreads();

    const float* sbias = (const float*)(smc + BIAS_OFF);
#pragma unroll
    for (int i = 0; i < 32; i++) {
        int idx = tid + i * NTHREADS;     // float4 index, 0..4095
        int row = idx >> 5;
        int c4 = idx & 31;
        float4 v = *reinterpret_cast<float4*>(&stage[row * EPI_LD + c4 * 4]);
        int n = c4 * 4;
        v.x += sbias[n + 0]; v.y += sbias[n + 1]; v.z += sbias[n + 2]; v.w += sbias[n + 3];
        size_t off = (size_t)g * CC * Ntot + (size_t)(mBase + row) * Ntot + nBase + n;
        if (mode == 0) {
            __half2 h0 = __floats2half2_rn(gelu_fast(v.x), gelu_fast(v.y));
            __half2 h1 = __floats2half2_rn(gelu_fast(v.z), gelu_fast(v.w));
            uint2 u;
            u.x = *reinterpret_cast<unsigned*>(&h0);
            u.y = *reinterpret_cast<unsigned*>(&h1);
            *reinterpret_cast<uint2*>(Oh + off) = u;
        } else {
            *reinterpret_cast<float4*>(outF + off) = v;
        }
    }
}

// ---------------- host launcher ----------------
extern "C" void kernel_launch(void* const* d_in, const int* in_sizes, int n_in,
                              void* d_out, int out_size) {
    const float* inputs = (const float*)d_in[0];
    const float* w1     = (const float*)d_in[1];
    const float* b1     = (const float*)d_in[2];
    const float* w2     = (const float*)d_in[3];
    const float* b2     = (const float*)d_in[4];
    float*       out    = (float*)d_out;

    void *xh, *w1t, *w2t, *hh;
    cudaGetSymbolAddress(&xh, g_Xh);
    cudaGetSymbolAddress(&w1t, g_W1t);
    cudaGetSymbolAddress(&w2t, g_W2t);
    cudaGetSymbolAddress(&hh, g_Hh);

    cudaFuncSetAttribute(moe_gemm, cudaFuncAttributeMaxDynamicSharedMemorySize, SMEM_TOTAL);

    // prepass
    {
        size_t n4 = (size_t)BB * EE * CC * DD / 4;
        to_fp16<<<(unsigned)((n4 + 255) / 256), 256>>>(inputs, (__half*)xh, n4);
    }
    {
        dim3 blk(32, 8);
        dim3 g1(FF / 32, DD / 32, EE);
        transpose_fp16<<<g1, blk>>>(w1, (__half*)w1t, DD, FF);
        dim3 g2(DD / 32, FF / 32, EE);
        transpose_fp16<<<g2, blk>>>(w2, (__half*)w2t, FF, DD);
    }

    // GEMM1: H = gelu(X @ W1^T + b1): per group M=1024, K=512, N=2048
    {
        dim3 grid(FF / BN, CC / BM, BB * EE);
        moe_gemm<<<grid, NTHREADS, SMEM_TOTAL>>>(
            (const __half*)xh, (const __half*)w1t, b1,
            nullptr, (__half*)hh, DD, FF, 0);
    }
    // GEMM2: Y = H @ W2^T + b2: per group M=1024, K=2048, N=512
    {
        dim3 grid(DD / BN, CC / BM, BB * EE);
        moe_gemm<<<grid, NTHREADS, SMEM_TOTAL>>>(
            (const __half*)hh, (const __half*)w2t, b2,
            out, nullptr, FF, DD, 1);
    }
}

// round 10
// speedup vs baseline: 1.7243x; 1.0931x over previous
#include <cuda_runtime.h>
#include <cuda_fp16.h>
#include <mma.h>
#include <cstdint>

using namespace nvcuda;

// ---------------- problem constants ----------------
#define BB 16
#define EE 8
#define CC 1024
#define DD 512
#define FF 2048

// ---------------- tiling (round-4 proven config) ----------------
#define BM 128
#define BN 128
#define BK 64
#define KS 72                          // smem row stride in halfs (144B)
#define A_ROWS 128
#define B_ROWS 128
#define STAGE_ELEMS ((A_ROWS + B_ROWS) * KS)
#define STAGE_BYTES (STAGE_ELEMS * 2)  // 36864
#define NSTAGE 3
#define SMEM_TOTAL (NSTAGE * STAGE_BYTES)   // 110592 -> 2 CTAs/SM
#define EPI_LD 132

// ---------------- scratch (device globals; no allocs) ----------------
__device__ __half g_Xh [(size_t)BB * EE * CC * DD];      // X  fp16
__device__ __half g_W1t[(size_t)EE * FF * DD];           // W1^T [e][n=F][k=D]
__device__ __half g_W2t[(size_t)EE * DD * FF];           // W2^T [e][n=D][k=F]
__device__ __half g_Hh [(size_t)BB * EE * CC * FF];      // H  fp16

// ---------------- PTX helpers ----------------
__device__ __forceinline__ uint32_t smem_u32(const void* p) {
    uint32_t a;
    asm("{ .reg .u64 t; cvta.to.shared.u64 t, %1; cvt.u32.u64 %0, t; }" : "=r"(a) : "l"(p));
    return a;
}
#define CP_ASYNC16(dst, src) \
    asm volatile("cp.async.cg.shared.global [%0], [%1], 16;" :: "r"(dst), "l"(src) : "memory")
#define CP_COMMIT()  asm volatile("cp.async.commit_group;" ::: "memory")
#define CP_WAIT1()   asm volatile("cp.async.wait_group 1;" ::: "memory")

// ---------------- math helpers (identical to round 4) ----------------
__device__ __forceinline__ float gelu_fast(float x) {
    float u = 0.7978845608028654f * fmaf(0.044715f * x, x * x, x);
    float y = 2.8853900817779268f * u;     // 2u / ln2
    float z;
    asm("ex2.approx.f32 %0, %1;" : "=f"(z) : "f"(y));
    float t = 1.0f - __fdividef(2.0f, z + 1.0f);
    return 0.5f * x * (1.0f + t);
}

// ---------------- prepass: fp32 -> fp16 (coalesced) ----------------
__global__ void to_fp16(const float* __restrict__ src, __half* __restrict__ dst, size_t n4) {
    size_t i = blockIdx.x * (size_t)blockDim.x + threadIdx.x;
    if (i >= n4) return;
    float4 v = reinterpret_cast<const float4*>(src)[i];
    __half2 h0 = __floats2half2_rn(v.x, v.y);
    __half2 h1 = __floats2half2_rn(v.z, v.w);
    uint2 u;
    u.x = *reinterpret_cast<unsigned*>(&h0);
    u.y = *reinterpret_cast<unsigned*>(&h1);
    reinterpret_cast<uint2*>(dst)[i] = u;
}

// ---------------- prepass: tiled transpose  w[e][K][N] -> t[e][N][K] fp16 ----------------
__global__ void transpose_fp16(const float* __restrict__ w, __half* __restrict__ t,
                               int K, int N) {
    __shared__ float tile[32][33];
    const int e = blockIdx.z;
    const int k0 = blockIdx.y * 32;
    const int n0 = blockIdx.x * 32;
    const float* we = w + (size_t)e * K * N;
#pragma unroll
    for (int i = 0; i < 4; i++) {
        int k = k0 + threadIdx.y + i * 8;
        tile[threadIdx.y + i * 8][threadIdx.x] = we[(size_t)k * N + n0 + threadIdx.x];
    }
    __syncthreads();
    __half* te = t + (size_t)e * N * K;
#pragma unroll
    for (int i = 0; i < 4; i++) {
        int n = n0 + threadIdx.y + i * 8;
        te[(size_t)n * K + k0 + threadIdx.x] = __float2half_rn(tile[threadIdx.x][threadIdx.y + i * 8]);
    }
}

// ---------------- main grouped GEMM (round-4 kernel, verbatim) ----------------
__global__ void __launch_bounds__(256, 2)
moe_gemm(const __half* __restrict__ Ah, const __half* __restrict__ Bh,
         const float* __restrict__ bias,
         float* __restrict__ outF, __half* __restrict__ Oh,
         int K, int Ntot, int mode)
{
    extern __shared__ char smc[];
    const uint32_t sbase = smem_u32(smc);
    const int tid = threadIdx.x;
    const int wid = tid >> 5;

    const int g = blockIdx.z;
    const int e = g & (EE - 1);
    const int mBase = blockIdx.y * BM;
    const int nBase = blockIdx.x * BN;

    const __half* aP = Ah + (size_t)g * CC * K + (size_t)mBase * K;
    const __half* bP = Bh + (size_t)e * Ntot * K + (size_t)nBase * K;

    const int KT = K / BK;

    auto loadStage = [&](int kt) {
        const int k0 = kt * BK;
        const uint32_t s = sbase + (uint32_t)((kt % NSTAGE) * STAGE_BYTES);
#pragma unroll
        for (int i = 0; i < 4; i++) {
            int idx = tid + i * 256;
            int row = idx >> 3, q = idx & 7;
            uint32_t d = s + (uint32_t)(row * (KS * 2) + q * 16);
            size_t go = (size_t)row * K + k0 + q * 8;
            CP_ASYNC16(d, aP + go);
            CP_ASYNC16(d + A_ROWS * KS * 2, bP + go);
        }
    };

    wmma::fragment<wmma::accumulator, 16, 16, 16, float> acc[4][2];
#pragma unroll
    for (int mi = 0; mi < 4; mi++)
#pragma unroll
        for (int ni = 0; ni < 2; ni++)
            wmma::fill_fragment(acc[mi][ni], 0.0f);

    const int wm = (wid & 1) * 64;
    const int wn = (wid >> 1) * 32;

    loadStage(0); CP_COMMIT();
    loadStage(1); CP_COMMIT();

    for (int kt = 0; kt < KT; kt++) {
        CP_WAIT1();
        __syncthreads();
        if (kt + 2 < KT) loadStage(kt + 2);
        CP_COMMIT();

        const __half* sA = (const __half*)(smc + (kt % NSTAGE) * STAGE_BYTES);
        const __half* sB = sA + A_ROWS * KS;

#pragma unroll
        for (int ks = 0; ks < 4; ks++) {
            wmma::fragment<wmma::matrix_a, 16, 16, 16, __half, wmma::row_major> fa[4];
            wmma::fragment<wmma::matrix_b, 16, 16, 16, __half, wmma::col_major> fb[2];
#pragma unroll
            for (int mi = 0; mi < 4; mi++)
                wmma::load_matrix_sync(fa[mi], sA + (wm + mi * 16) * KS + ks * 16, KS);
#pragma unroll
            for (int ni = 0; ni < 2; ni++)
                wmma::load_matrix_sync(fb[ni], sB + (wn + ni * 16) * KS + ks * 16, KS);
#pragma unroll
            for (int mi = 0; mi < 4; mi++)
#pragma unroll
                for (int ni = 0; ni < 2; ni++)
                    wmma::mma_sync(acc[mi][ni], fa[mi], fb[ni], acc[mi][ni]);
        }
    }

    __syncthreads();
    float* stage = reinterpret_cast<float*>(smc);
#pragma unroll
    for (int mi = 0; mi < 4; mi++)
#pragma unroll
        for (int ni = 0; ni < 2; ni++)
            wmma::store_matrix_sync(&stage[(wm + mi * 16) * EPI_LD + wn + ni * 16],
                                    acc[mi][ni], EPI_LD, wmma::mem_row_major);
    __syncthreads();

#pragma unroll
    for (int i = 0; i < 16; i++) {
        int idx = tid + i * 256;
        int row = idx >> 5;
        int c4 = idx & 31;
        float4 v = *reinterpret_cast<float4*>(&stage[row * EPI_LD + c4 * 4]);
        int n = nBase + c4 * 4;
        v.x += bias[n + 0]; v.y += bias[n + 1]; v.z += bias[n + 2]; v.w += bias[n + 3];
        size_t off = (size_t)g * CC * Ntot + (size_t)(mBase + row) * Ntot + n;
        if (mode == 0) {
            __half2 h0 = __floats2half2_rn(gelu_fast(v.x), gelu_fast(v.y));
            __half2 h1 = __floats2half2_rn(gelu_fast(v.z), gelu_fast(v.w));
            uint2 u;
            u.x = *reinterpret_cast<unsigned*>(&h0);
            u.y = *reinterpret_cast<unsigned*>(&h1);
            *reinterpret_cast<uint2*>(Oh + off) = u;
        } else {
            *reinterpret_cast<float4*>(outF + off) = v;
        }
    }
}

// ---------------- host launcher with fork/join stream overlap ----------------
static cudaStream_t g_s1 = nullptr, g_s2 = nullptr;
static cudaEvent_t g_e0, g_e1, g_e2;
static bool g_init = false;

extern "C" void kernel_launch(void* const* d_in, const int* in_sizes, int n_in,
                              void* d_out, int out_size) {
    const float* inputs = (const float*)d_in[0];
    const float* w1     = (const float*)d_in[1];
    const float* b1     = (const float*)d_in[2];
    const float* w2     = (const float*)d_in[3];
    const float* b2     = (const float*)d_in[4];
    float*       out    = (float*)d_out;

    void *xh, *w1t, *w2t, *hh;
    cudaGetSymbolAddress(&xh, g_Xh);
    cudaGetSymbolAddress(&w1t, g_W1t);
    cudaGetSymbolAddress(&w2t, g_W2t);
    cudaGetSymbolAddress(&hh, g_Hh);

    if (!g_init) {
        cudaStreamCreateWithFlags(&g_s1, cudaStreamNonBlocking);
        cudaStreamCreateWithFlags(&g_s2, cudaStreamNonBlocking);
        cudaEventCreateWithFlags(&g_e0, cudaEventDisableTiming);
        cudaEventCreateWithFlags(&g_e1, cudaEventDisableTiming);
        cudaEventCreateWithFlags(&g_e2, cudaEventDisableTiming);
        cudaFuncSetAttribute(moe_gemm, cudaFuncAttributeMaxDynamicSharedMemorySize, SMEM_TOTAL);
        g_init = true;
    }

    // fork: side streams wait on the main stream's current point
    cudaEventRecord(g_e0, 0);
    cudaStreamWaitEvent(g_s1, g_e0, 0);
    cudaStreamWaitEvent(g_s2, g_e0, 0);

    // main stream: X convert (GEMM1's critical input)
    {
        size_t n4 = (size_t)BB * EE * CC * DD / 4;
        to_fp16<<<(unsigned)((n4 + 255) / 256), 256, 0, 0>>>(inputs, (__half*)xh, n4);
    }
    // s1: W1 transpose (needed before GEMM1)
    {
        dim3 blk(32, 8);
        dim3 gr(FF / 32, DD / 32, EE);
        transpose_fp16<<<gr, blk, 0, g_s1>>>(w1, (__half*)w1t, DD, FF);
        cudaEventRecord(g_e1, g_s1);
    }
    // s2: W2 transpose (only needed before GEMM2 -> hidden under GEMM1)
    {
        dim3 blk(32, 8);
        dim3 gr(DD / 32, FF / 32, EE);
        transpose_fp16<<<gr, blk, 0, g_s2>>>(w2, (__half*)w2t, FF, DD);
        cudaEventRecord(g_e2, g_s2);
    }

    // join W1t, then GEMM1: H = gelu(X @ W1^T + b1)
    cudaStreamWaitEvent(0, g_e1, 0);
    {
        dim3 grid(FF / BN, CC / BM, BB * EE);
        moe_gemm<<<grid, 256, SMEM_TOTAL, 0>>>(
            (const __half*)xh, (const __half*)w1t, b1,
            nullptr, (__half*)hh, DD, FF, 0);
    }

    // join W2t, then GEMM2: Y = H @ W2^T + b2
    cudaStreamWaitEvent(0, g_e2, 0);
    {
        dim3 grid(DD / BN, CC / BM, BB * EE);
        moe_gemm<<<grid, 256, SMEM_TOTAL, 0>>>(
            (const __half*)hh, (const __half*)w2t, b2,
            out, nullptr, FF, DD, 1);
    }
}